// round 4
// baseline (speedup 1.0000x reference)
#include <cuda_runtime.h>
#include <math.h>

// Problem constants
#define BB 2
#define SS 4096
#define EE 512
#define HH 8
#define DD 64
#define WW 512
#define NWIN 8            // SS / WW
#define NBUCKETS 32

#define NEGINF (-INFINITY)

typedef unsigned long long ull;

// Scratch: q,k,v in [b][h][s][d] layout (16 MB each)
__device__ float g_q[BB*HH*SS*DD];
__device__ float g_k[BB*HH*SS*DD];
__device__ float g_v[BB*HH*SS*DD];

// ---------------------------------------------------------------------------
// packed f32x2 helpers (FFMA2 path, sm_103a)
// ---------------------------------------------------------------------------
__device__ __forceinline__ ull pack2(float x, float y) {
    ull r; asm("mov.b64 %0, {%1,%2};" : "=l"(r) : "f"(x), "f"(y)); return r;
}
__device__ __forceinline__ float2 unpack2(ull v) {
    float2 f; asm("mov.b64 {%0,%1}, %2;" : "=f"(f.x), "=f"(f.y) : "l"(v)); return f;
}
__device__ __forceinline__ ull fma2(ull a, ull b, ull c) {
    ull d; asm("fma.rn.f32x2 %0, %1, %2, %3;" : "=l"(d) : "l"(a), "l"(b), "l"(c)); return d;
}
__device__ __forceinline__ ull mul2(ull a, ull b) {
    ull d; asm("mul.rn.f32x2 %0, %1, %2;" : "=l"(d) : "l"(a), "l"(b)); return d;
}

// ---------------------------------------------------------------------------
// Projection: out[b][h][s][d] = sum_e xs[b,s,e] * w[e,h,d]   (q scaled 0.125)
// SGEMM: M=8192, N=512, K=512.  128x128 tile, 8x8 microtile, f32x2 FMAs.
// ---------------------------------------------------------------------------
__global__ __launch_bounds__(256) void proj_kernel(
    const float* __restrict__ xs,
    const float* __restrict__ wq,
    const float* __restrict__ wk,
    const float* __restrict__ wv)
{
    const int zb = blockIdx.z;
    const float* w   = (zb == 0) ? wq : (zb == 1) ? wk : wv;
    float*       out = (zb == 0) ? g_q : (zb == 1) ? g_k : g_v;
    const float scale = (zb == 0) ? 0.125f : 1.0f;   // 1/sqrt(D)

    __shared__ __align__(16) float As[16][128];   // [k][m]
    __shared__ __align__(16) float Bs[16][128];   // [k][n]

    const int m0 = blockIdx.x * 128;
    const int n0 = blockIdx.y * 128;
    const int tid = threadIdx.x;
    const int tr = tid / 16;     // 0..15
    const int tc = tid % 16;     // 0..15

    ull acc2[8][4];
    const ull z2 = pack2(0.0f, 0.0f);
    #pragma unroll
    for (int i = 0; i < 8; i++)
        #pragma unroll
        for (int j = 0; j < 4; j++) acc2[i][j] = z2;

    for (int k0 = 0; k0 < EE; k0 += 16) {
        // Load A tile (128 rows x 16 k) transposed into As[k][m]
        #pragma unroll
        for (int i = 0; i < 2; i++) {
            int idx = tid + i * 256;           // 0..511
            int row = idx >> 2;                // 0..127
            int c4  = idx & 3;                 // 0..3
            float4 v = *(const float4*)(xs + (size_t)(m0 + row) * EE + k0 + c4 * 4);
            As[c4*4+0][row] = v.x;
            As[c4*4+1][row] = v.y;
            As[c4*4+2][row] = v.z;
            As[c4*4+3][row] = v.w;
        }
        // Load B tile (16 k x 128 n)
        #pragma unroll
        for (int i = 0; i < 2; i++) {
            int idx = tid + i * 256;           // 0..511
            int row = idx >> 5;                // 0..15
            int c4  = idx & 31;                // 0..31
            float4 v = *(const float4*)(w + (size_t)(k0 + row) * (HH*DD) + n0 + c4 * 4);
            *(float4*)&Bs[row][c4 * 4] = v;
        }
        __syncthreads();

        #pragma unroll
        for (int kk = 0; kk < 16; kk++) {
            float4 a0 = *(const float4*)&As[kk][tr * 8];
            float4 a1 = *(const float4*)&As[kk][tr * 8 + 4];
            float4 b0 = *(const float4*)&Bs[kk][tc * 8];
            float4 b1 = *(const float4*)&Bs[kk][tc * 8 + 4];
            float av[8] = {a0.x, a0.y, a0.z, a0.w, a1.x, a1.y, a1.z, a1.w};
            ull bb[4];
            bb[0] = pack2(b0.x, b0.y);
            bb[1] = pack2(b0.z, b0.w);
            bb[2] = pack2(b1.x, b1.y);
            bb[3] = pack2(b1.z, b1.w);
            #pragma unroll
            for (int i = 0; i < 8; i++) {
                ull av2 = pack2(av[i], av[i]);
                #pragma unroll
                for (int j = 0; j < 4; j++)
                    acc2[i][j] = fma2(av2, bb[j], acc2[i][j]);
            }
        }
        __syncthreads();
    }

    // Epilogue: scatter into [b][h][s][d].
    const int b = m0 / SS;
    const int cbase = n0 + tc * 8;
    const int h = cbase / DD;
    const int d = cbase % DD;
    #pragma unroll
    for (int i = 0; i < 8; i++) {
        int m = m0 + tr * 8 + i;
        int s = m - b * SS;
        float* dst = out + (((size_t)(b * HH + h) * SS + s) * DD + d);
        #pragma unroll
        for (int j = 0; j < 4; j++) {
            float2 v = unpack2(acc2[i][j]);
            dst[2*j]   = v.x * scale;
            dst[2*j+1] = v.y * scale;
        }
    }
}

// ---------------------------------------------------------------------------
// Attention: sliding-window causal (key g in (p-W, p]) with T5 relative bias.
// One thread per query; online softmax with conditional rescale; f32x2 math.
// Block = 128 threads = 128 queries; grid = (4 chunks, H, B*nw).
// ---------------------------------------------------------------------------
__global__ __launch_bounds__(128) void attn_kernel(
    const float* __restrict__ prev_k,
    const float* __restrict__ prev_v,
    const float* __restrict__ rel_bias,
    float* __restrict__ out)
{
    const int chunk = blockIdx.x;          // 0..3
    const int h     = blockIdx.y;          // 0..7
    const int bn    = blockIdx.z;          // 0..15
    const int b = bn / NWIN;
    const int n = bn % NWIN;
    const int t = threadIdx.x;

    __shared__ __align__(16) float Ks[64][64];
    __shared__ __align__(16) float Vs[64][64];
    __shared__ float bias_s[WW];

    // Build per-head bias table: bias_s[nrel] for nrel = (query - key) in [0, W)
    for (int i = t; i < WW; i += 128) {
        int bucket;
        if (i < 16) {
            bucket = i;
        } else {
            float nf = (float)i;
            float tv = logf(nf * 0.0625f) / 2.0794415416798357f * 16.0f;
            int vi = 16 + (int)tv;
            bucket = (vi < NBUCKETS - 1) ? vi : (NBUCKETS - 1);
        }
        bias_s[i] = rel_bias[h * NBUCKETS + bucket];
    }

    const int q0 = n * WW + chunk * 128;     // first query (abs) of this block
    const int p  = q0 + t;                   // this thread's query position

    // Load query row into packed registers (32 f32x2 pairs)
    ull q2[32];
    {
        const float* qp = g_q + (((size_t)(b * HH + h) * SS + p) * DD);
        #pragma unroll
        for (int i = 0; i < 16; i++) {
            float4 v = *(const float4*)(qp + i * 4);
            q2[2*i]   = pack2(v.x, v.y);
            q2[2*i+1] = pack2(v.z, v.w);
        }
    }

    const ull z2 = pack2(0.0f, 0.0f);
    ull acc2[32];
    #pragma unroll
    for (int i = 0; i < 32; i++) acc2[i] = z2;
    float mrun = -1e30f;
    float lrun = 0.0f;

    const int kt0 = q0 - WW;                 // first key tile start
    const int pbase = q0 + (t & ~31);        // warp's first query

    for (int tile = 0; tile < 10; tile++) {
        const int kt = kt0 + tile * 64;
        __syncthreads();
        // Cooperative load of 64 keys + 64 values (each thread 8+8 float4)
        for (int i = t; i < 64 * 16; i += 128) {
            int row = i >> 4;
            int c4  = i & 15;
            int g = kt + row;
            const float *sk, *sv;
            if (g < 0) {   // previous-window K/V (only window 0)
                size_t off = (((size_t)(b * WW + (g + WW)) * HH + h) * DD) + c4 * 4;
                sk = prev_k + off;  sv = prev_v + off;
            } else {
                size_t off = (((size_t)(b * HH + h) * SS + g) * DD) + c4 * 4;
                sk = g_k + off;     sv = g_v + off;
            }
            *(float4*)&Ks[row][c4 * 4] = *(const float4*)sk;
            *(float4*)&Vs[row][c4 * 4] = *(const float4*)sv;
        }
        __syncthreads();

        // Warp-uniform loop bounds (keeps Ks/Vs reads broadcast)
        int jloW = pbase - (WW - 1) - kt; if (jloW < 0) jloW = 0;
        int jhiW = pbase + 31 - kt;       if (jhiW > 63) jhiW = 63;

        for (int j = jloW; j <= jhiW; j++) {
            int rel = p - (kt + j);                       // query - key
            bool act = (rel >= 0) && (rel < WW);
            float s = act ? bias_s[rel & (WW - 1)] : NEGINF;

            // QK dot: 32 packed FMAs into 4 packed accumulators
            const float* kr = &Ks[j][0];
            ull dp[4] = {z2, z2, z2, z2};
            #pragma unroll
            for (int d4 = 0; d4 < 16; d4++) {
                float4 kv = *(const float4*)(kr + d4 * 4);
                ull k0p = pack2(kv.x, kv.y);
                ull k1p = pack2(kv.z, kv.w);
                dp[(2*d4)   & 3] = fma2(q2[2*d4],   k0p, dp[(2*d4)   & 3]);
                dp[(2*d4+1) & 3] = fma2(q2[2*d4+1], k1p, dp[(2*d4+1) & 3]);
            }
            float2 r0 = unpack2(dp[0]);
            float2 r1 = unpack2(dp[1]);
            float2 r2 = unpack2(dp[2]);
            float2 r3 = unpack2(dp[3]);
            s += ((r0.x + r0.y) + (r1.x + r1.y)) + ((r2.x + r2.y) + (r3.x + r3.y));

            if (s > mrun) {                 // rare: rescale running state
                float c = __expf(mrun - s);
                lrun *= c;
                ull c2 = pack2(c, c);
                #pragma unroll
                for (int i = 0; i < 32; i++) acc2[i] = mul2(acc2[i], c2);
                mrun = s;
            }
            float pw = __expf(s - mrun);    // 0 for masked (s = -inf)
            lrun += pw;

            const float* vr = &Vs[j][0];
            ull pw2 = pack2(pw, pw);
            #pragma unroll
            for (int d4 = 0; d4 < 16; d4++) {
                float4 vv = *(const float4*)(vr + d4 * 4);
                acc2[2*d4]   = fma2(pw2, pack2(vv.x, vv.y), acc2[2*d4]);
                acc2[2*d4+1] = fma2(pw2, pack2(vv.z, vv.w), acc2[2*d4+1]);
            }
        }
    }

    // Write attn output: (B, S, H, D)
    const float inv = 1.0f / lrun;
    float* op = out + (((size_t)(b * SS + p) * HH + h) * DD);
    #pragma unroll
    for (int d4 = 0; d4 < 16; d4++) {
        float2 lo = unpack2(acc2[2*d4]);
        float2 hi = unpack2(acc2[2*d4+1]);
        float4 o;
        o.x = lo.x * inv;
        o.y = lo.y * inv;
        o.z = hi.x * inv;
        o.w = hi.y * inv;
        *(float4*)(op + d4 * 4) = o;
    }
}

// ---------------------------------------------------------------------------
// Tail: next_k / next_v = last window of k / v, layout (B, W, H, D)
// ---------------------------------------------------------------------------
__global__ __launch_bounds__(256) void tail_kernel(float* __restrict__ out)
{
    const size_t OFF_K = (size_t)BB * SS * HH * DD;             // 4194304
    const size_t OFF_V = OFF_K + (size_t)BB * WW * HH * DD;     // 4718592
    int i = blockIdx.x * 256 + threadIdx.x;                     // < 524288
    int b = i / (WW * HH * DD);
    int r = i % (WW * HH * DD);
    int w = r / (HH * DD);
    int r2 = r % (HH * DD);
    int h = r2 / DD;
    int d = r2 % DD;
    size_t src = (((size_t)(b * HH + h) * SS + (SS - WW + w)) * DD + d);
    out[OFF_K + i] = g_k[src];
    out[OFF_V + i] = g_v[src];
}

// ---------------------------------------------------------------------------
extern "C" void kernel_launch(void* const* d_in, const int* in_sizes, int n_in,
                              void* d_out, int out_size)
{
    const float* xs       = (const float*)d_in[0];
    const float* prev_k   = (const float*)d_in[1];
    const float* prev_v   = (const float*)d_in[2];
    const float* w_q      = (const float*)d_in[3];
    const float* w_k      = (const float*)d_in[4];
    const float* w_v      = (const float*)d_in[5];
    const float* rel_bias = (const float*)d_in[6];
    float* out = (float*)d_out;

    dim3 pg(64, 4, 3);                 // M/128, N/128, {q,k,v}
    proj_kernel<<<pg, 256>>>(xs, w_q, w_k, w_v);

    dim3 ag(4, HH, BB * NWIN);         // query chunks, heads, batch*windows
    attn_kernel<<<ag, 128>>>(prev_k, prev_v, rel_bias, out);

    tail_kernel<<<2048, 256>>>(out);
}

// round 5
// speedup vs baseline: 1.5671x; 1.5671x over previous
#include <cuda_runtime.h>
#include <math.h>

// Problem constants
#define BB 2
#define SS 4096
#define EE 512
#define HH 8
#define DD 64
#define WW 512
#define NWIN 8            // SS / WW
#define NBUCKETS 32

#define NEGINF (-INFINITY)

// Scratch: q,k,v in [b][h][s][d] layout (16 MB each)
__device__ float g_q[BB*HH*SS*DD];
__device__ float g_k[BB*HH*SS*DD];
__device__ float g_v[BB*HH*SS*DD];

// tf32 hi/lo splits, k-permuted within 16-chunks
__device__ unsigned g_xs_hi[BB*SS*EE];          // [m][kperm], m = b*S+s
__device__ unsigned g_xs_lo[BB*SS*EE];
__device__ unsigned g_w_hi[3*EE*HH*DD];         // [zb][n][kperm]  (transposed)
__device__ unsigned g_w_lo[3*EE*HH*DD];

// ---------------------------------------------------------------------------
// tf32 helpers
// ---------------------------------------------------------------------------
__device__ __forceinline__ unsigned f2tf32(float x) {
    unsigned r;
    asm("cvt.rna.tf32.f32 %0, %1;" : "=r"(r) : "f"(x));
    return r;
}

__device__ __forceinline__ void mma_tf32(float c[4], const unsigned a[4], const unsigned b[2]) {
    asm volatile(
        "mma.sync.aligned.m16n8k8.row.col.f32.tf32.tf32.f32 "
        "{%0,%1,%2,%3}, {%4,%5,%6,%7}, {%8,%9}, {%0,%1,%2,%3};"
        : "+f"(c[0]), "+f"(c[1]), "+f"(c[2]), "+f"(c[3])
        : "r"(a[0]), "r"(a[1]), "r"(a[2]), "r"(a[3]), "r"(b[0]), "r"(b[1]));
}

__device__ __forceinline__ void cp16(unsigned s, const void* g) {
    asm volatile("cp.async.cg.shared.global [%0], [%1], 16;" :: "r"(s), "l"(g));
}
__device__ __forceinline__ void cp_commit() {
    asm volatile("cp.async.commit_group;");
}
__device__ __forceinline__ void cp_wait1() {
    asm volatile("cp.async.wait_group 1;");
}
__device__ __forceinline__ void cp_wait0() {
    asm volatile("cp.async.wait_group 0;");
}

// permutation within a 16-element k chunk (self-inverse)
__device__ __forceinline__ int kperm(int k) {
    return (k & ~15) | ((k & 3) << 2) | ((k >> 2) & 3);
}

// ---------------------------------------------------------------------------
// Pre-split xs: fp32 -> (tf32 hi, tf32 lo), permuted k layout [m][kperm]
// ---------------------------------------------------------------------------
__global__ __launch_bounds__(256) void split_xs_kernel(const float* __restrict__ xs)
{
    int id = blockIdx.x * 256 + threadIdx.x;       // < B*S*E = 4M
    float x = xs[id];
    unsigned hi = f2tf32(x);
    float lo = x - __uint_as_float(hi);
    int m = id >> 9;
    int k = id & 511;
    int o = (m << 9) | kperm(k);
    g_xs_hi[o] = hi;
    g_xs_lo[o] = f2tf32(lo);
}

// ---------------------------------------------------------------------------
// Pre-split weights: transpose [e][n] -> [n][e], split, permute e.
// grid (16, 16, 3), block 256 (32x8 tile loop).
// ---------------------------------------------------------------------------
__global__ __launch_bounds__(256) void split_w_kernel(
    const float* __restrict__ wq,
    const float* __restrict__ wk,
    const float* __restrict__ wv)
{
    const int zb = blockIdx.z;
    const float* w = (zb == 0) ? wq : (zb == 1) ? wk : wv;

    __shared__ float th[32][33];
    __shared__ float tl[32][33];

    const int e0 = blockIdx.x * 32;
    const int n0 = blockIdx.y * 32;
    const int lx = threadIdx.x & 31;
    const int ly = threadIdx.x >> 5;   // 0..7

    #pragma unroll
    for (int r = 0; r < 4; r++) {
        int e = e0 + ly + r * 8;
        float x = w[e * 512 + n0 + lx];
        unsigned hi = f2tf32(x);
        th[lx][ly + r * 8] = __uint_as_float(hi);
        tl[lx][ly + r * 8] = __uint_as_float(f2tf32(x - __uint_as_float(hi)));
    }
    __syncthreads();

    const int ep = e0 + (lx & 16) + ((lx & 3) << 2) + ((lx >> 2) & 3);
    #pragma unroll
    for (int r = 0; r < 4; r++) {
        int n = n0 + ly + r * 8;
        size_t o = (size_t)(zb * 512 + n) * 512 + ep;
        g_w_hi[o] = __float_as_uint(th[ly + r * 8][lx]);
        g_w_lo[o] = __float_as_uint(tl[ly + r * 8][lx]);
    }
}

// ---------------------------------------------------------------------------
// Projection via 3xTF32 tensor-core GEMM with cp.async double buffering.
// out[b][h][s][d] = sum_e xs[b,s,e] * w[e,h,d]   (q scaled 0.125)
// M=8192, N=512, K=512.  128x128 block tile, 8 warps (2x4), warp 64x32.
// smem: 2 buffers x {Ahi, Alo, Bhi, Blo} x 128x16 floats = 64 KB dynamic.
// ---------------------------------------------------------------------------
__global__ __launch_bounds__(256) void proj_kernel()
{
    extern __shared__ float smem[];   // [2][4][2048]

    const int zb = blockIdx.z;
    float* out = (zb == 0) ? g_q : (zb == 1) ? g_k : g_v;
    const float scale = (zb == 0) ? 0.125f : 1.0f;

    const int m0 = blockIdx.x * 128;
    const int n0 = blockIdx.y * 128;
    const int tid  = threadIdx.x;
    const int wid  = tid >> 5;
    const int lane = tid & 31;
    const int g    = lane >> 2;     // 0..7
    const int tg   = lane & 3;      // 0..3
    const int wm   = wid >> 2;      // 0..1
    const int wn   = wid & 3;       // 0..3

    unsigned smem_u32;
    {
        void* p = smem;
        asm("{ .reg .u64 t; cvta.to.shared.u64 t, %1; cvt.u32.u64 %0, t; }"
            : "=r"(smem_u32) : "l"(p));
    }

    // staging addresses for this thread (2 float4 slots per array)
    // idx = tid*2 + it : row = idx>>2 (0..127), c4 = idx&3
    int row0 = (tid * 2)     >> 2, c40 = (tid * 2)     & 3;
    int row1 = (tid * 2 + 1) >> 2, c41 = (tid * 2 + 1) & 3;

    float acc[4][4][4];
    #pragma unroll
    for (int mt = 0; mt < 4; mt++)
        #pragma unroll
        for (int nt = 0; nt < 4; nt++)
            #pragma unroll
            for (int r = 0; r < 4; r++) acc[mt][nt][r] = 0.0f;

    // ---- staging lambda ----
    auto stage = [&](int buf, int k0) {
        unsigned base = smem_u32 + (unsigned)buf * 4 * 2048 * 4;
        // A rows
        {
            const unsigned* srcH = g_xs_hi + ((m0 + row0) * 512 + k0 + c40 * 4);
            const unsigned* srcL = g_xs_lo + ((m0 + row0) * 512 + k0 + c40 * 4);
            unsigned d = base + (unsigned)(row0 * 16 + c40 * 4) * 4;
            cp16(d,                srcH);
            cp16(d + 2048 * 4,     srcL);
            const unsigned* srcH1 = g_xs_hi + ((m0 + row1) * 512 + k0 + c41 * 4);
            const unsigned* srcL1 = g_xs_lo + ((m0 + row1) * 512 + k0 + c41 * 4);
            unsigned d1 = base + (unsigned)(row1 * 16 + c41 * 4) * 4;
            cp16(d1,               srcH1);
            cp16(d1 + 2048 * 4,    srcL1);
        }
        // B rows
        {
            const unsigned* srcH = g_w_hi + ((size_t)(zb * 512 + n0 + row0) * 512 + k0 + c40 * 4);
            const unsigned* srcL = g_w_lo + ((size_t)(zb * 512 + n0 + row0) * 512 + k0 + c40 * 4);
            unsigned d = base + (unsigned)(2 * 2048 + row0 * 16 + c40 * 4) * 4;
            cp16(d,                srcH);
            cp16(d + 2048 * 4,     srcL);
            const unsigned* srcH1 = g_w_hi + ((size_t)(zb * 512 + n0 + row1) * 512 + k0 + c41 * 4);
            const unsigned* srcL1 = g_w_lo + ((size_t)(zb * 512 + n0 + row1) * 512 + k0 + c41 * 4);
            unsigned d1 = base + (unsigned)(2 * 2048 + row1 * 16 + c41 * 4) * 4;
            cp16(d1,               srcH1);
            cp16(d1 + 2048 * 4,    srcL1);
        }
    };

    stage(0, 0);
    cp_commit();

    for (int c = 0; c < 32; c++) {
        if (c < 31) {
            stage((c + 1) & 1, (c + 1) * 16);
            cp_commit();
            cp_wait1();
        } else {
            cp_wait0();
        }
        __syncthreads();

        const float* Ah = smem + ((c & 1) * 4 + 0) * 2048;
        const float* Al = smem + ((c & 1) * 4 + 1) * 2048;
        const float* Bh = smem + ((c & 1) * 4 + 2) * 2048;
        const float* Bl = smem + ((c & 1) * 4 + 3) * 2048;

        // fragment loads: one LDS.128 covers both k8 steps
        float4 aH[4][2], aL[4][2], bH[4], bL[4];
        #pragma unroll
        for (int mt = 0; mt < 4; mt++) {
            int r0 = (wm * 64 + mt * 16 + g) * 16 + tg * 4;
            int r1 = r0 + 8 * 16;
            aH[mt][0] = *(const float4*)(Ah + r0);
            aH[mt][1] = *(const float4*)(Ah + r1);
            aL[mt][0] = *(const float4*)(Al + r0);
            aL[mt][1] = *(const float4*)(Al + r1);
        }
        #pragma unroll
        for (int nt = 0; nt < 4; nt++) {
            int c0 = (wn * 32 + nt * 8 + g) * 16 + tg * 4;
            bH[nt] = *(const float4*)(Bh + c0);
            bL[nt] = *(const float4*)(Bl + c0);
        }

        // step 0: a = {f.x(row g), f.x(row g+8), f.y(row g), f.y(row g+8)}
        #pragma unroll
        for (int step = 0; step < 2; step++) {
            #pragma unroll
            for (int mt = 0; mt < 4; mt++) {
                unsigned ah[4], al[4];
                if (step == 0) {
                    ah[0] = __float_as_uint(aH[mt][0].x); ah[1] = __float_as_uint(aH[mt][1].x);
                    ah[2] = __float_as_uint(aH[mt][0].y); ah[3] = __float_as_uint(aH[mt][1].y);
                    al[0] = __float_as_uint(aL[mt][0].x); al[1] = __float_as_uint(aL[mt][1].x);
                    al[2] = __float_as_uint(aL[mt][0].y); al[3] = __float_as_uint(aL[mt][1].y);
                } else {
                    ah[0] = __float_as_uint(aH[mt][0].z); ah[1] = __float_as_uint(aH[mt][1].z);
                    ah[2] = __float_as_uint(aH[mt][0].w); ah[3] = __float_as_uint(aH[mt][1].w);
                    al[0] = __float_as_uint(aL[mt][0].z); al[1] = __float_as_uint(aL[mt][1].z);
                    al[2] = __float_as_uint(aL[mt][0].w); al[3] = __float_as_uint(aL[mt][1].w);
                }
                #pragma unroll
                for (int nt = 0; nt < 4; nt++) {
                    unsigned bh[2], bl[2];
                    if (step == 0) {
                        bh[0] = __float_as_uint(bH[nt].x); bh[1] = __float_as_uint(bH[nt].y);
                        bl[0] = __float_as_uint(bL[nt].x); bl[1] = __float_as_uint(bL[nt].y);
                    } else {
                        bh[0] = __float_as_uint(bH[nt].z); bh[1] = __float_as_uint(bH[nt].w);
                        bl[0] = __float_as_uint(bL[nt].z); bl[1] = __float_as_uint(bL[nt].w);
                    }
                    mma_tf32(acc[mt][nt], ah, bh);
                    mma_tf32(acc[mt][nt], ah, bl);
                    mma_tf32(acc[mt][nt], al, bh);
                }
            }
        }
        __syncthreads();
    }

    // --- Epilogue: scatter to [b][h][s][d] ---
    const int b = m0 / SS;
    #pragma unroll
    for (int mt = 0; mt < 4; mt++) {
        int m_lo = m0 + wm * 64 + mt * 16 + g;     // rows g and g+8
        #pragma unroll
        for (int nt = 0; nt < 4; nt++) {
            int n = n0 + wn * 32 + nt * 8 + tg * 2;
            int h = n / DD;
            int d = n % DD;
            {
                int s = m_lo - b * SS;
                float2 v; v.x = acc[mt][nt][0] * scale; v.y = acc[mt][nt][1] * scale;
                *(float2*)(out + (((size_t)(b * HH + h) * SS + s) * DD + d)) = v;
            }
            {
                int s = m_lo + 8 - b * SS;
                float2 v; v.x = acc[mt][nt][2] * scale; v.y = acc[mt][nt][3] * scale;
                *(float2*)(out + (((size_t)(b * HH + h) * SS + s) * DD + d)) = v;
            }
        }
    }
}

// ---------------------------------------------------------------------------
// Attention: sliding-window causal (key g in (p-W, p]) with T5 relative bias.
// One thread per query; online softmax with conditional rescale.
// Block = 128 threads = 128 queries; grid = (4 chunks, H, B*nw).
// ---------------------------------------------------------------------------
__global__ __launch_bounds__(128) void attn_kernel(
    const float* __restrict__ prev_k,
    const float* __restrict__ prev_v,
    const float* __restrict__ rel_bias,
    float* __restrict__ out)
{
    const int chunk = blockIdx.x;          // 0..3
    const int h     = blockIdx.y;          // 0..7
    const int bn    = blockIdx.z;          // 0..15
    const int b = bn / NWIN;
    const int n = bn % NWIN;
    const int t = threadIdx.x;

    __shared__ __align__(16) float Ks[64][64];
    __shared__ __align__(16) float Vs[64][64];
    __shared__ float bias_s[WW];

    for (int i = t; i < WW; i += 128) {
        int bucket;
        if (i < 16) {
            bucket = i;
        } else {
            float nf = (float)i;
            float tv = logf(nf * 0.0625f) / 2.0794415416798357f * 16.0f;
            int vi = 16 + (int)tv;
            bucket = (vi < NBUCKETS - 1) ? vi : (NBUCKETS - 1);
        }
        bias_s[i] = rel_bias[h * NBUCKETS + bucket];
    }

    const int q0 = n * WW + chunk * 128;
    const int p  = q0 + t;

    float qreg[64];
    {
        const float* qp = g_q + (((size_t)(b * HH + h) * SS + p) * DD);
        #pragma unroll
        for (int i = 0; i < 16; i++)
            ((float4*)qreg)[i] = *(const float4*)(qp + i * 4);
    }

    float acc[64];
    #pragma unroll
    for (int d = 0; d < 64; d++) acc[d] = 0.0f;
    float mrun = -1e30f;
    float lrun = 0.0f;

    const int kt0 = q0 - WW;
    const int pbase = q0 + (t & ~31);

    for (int tile = 0; tile < 10; tile++) {
        const int kt = kt0 + tile * 64;
        __syncthreads();
        for (int i = t; i < 64 * 16; i += 128) {
            int row = i >> 4;
            int c4  = i & 15;
            int g = kt + row;
            const float *sk, *sv;
            if (g < 0) {
                size_t off = (((size_t)(b * WW + (g + WW)) * HH + h) * DD) + c4 * 4;
                sk = prev_k + off;  sv = prev_v + off;
            } else {
                size_t off = (((size_t)(b * HH + h) * SS + g) * DD) + c4 * 4;
                sk = g_k + off;     sv = g_v + off;
            }
            *(float4*)&Ks[row][c4 * 4] = *(const float4*)sk;
            *(float4*)&Vs[row][c4 * 4] = *(const float4*)sv;
        }
        __syncthreads();

        int jloW = pbase - (WW - 1) - kt; if (jloW < 0) jloW = 0;
        int jhiW = pbase + 31 - kt;       if (jhiW > 63) jhiW = 63;

        for (int j = jloW; j <= jhiW; j++) {
            int rel = p - (kt + j);
            bool act = (rel >= 0) && (rel < WW);
            float s = act ? bias_s[rel & (WW - 1)] : NEGINF;

            const float* kr = &Ks[j][0];
            float d0 = 0.f, d1 = 0.f, d2 = 0.f, d3 = 0.f;
            #pragma unroll
            for (int d4 = 0; d4 < 16; d4++) {
                float4 kv = *(const float4*)(kr + d4 * 4);
                d0 += qreg[d4*4+0] * kv.x;
                d1 += qreg[d4*4+1] * kv.y;
                d2 += qreg[d4*4+2] * kv.z;
                d3 += qreg[d4*4+3] * kv.w;
            }
            s += (d0 + d1) + (d2 + d3);

            if (s > mrun) {
                float c = __expf(mrun - s);
                lrun *= c;
                #pragma unroll
                for (int d = 0; d < 64; d++) acc[d] *= c;
                mrun = s;
            }
            float pw = __expf(s - mrun);
            lrun += pw;

            const float* vr = &Vs[j][0];
            #pragma unroll
            for (int d4 = 0; d4 < 16; d4++) {
                float4 vv = *(const float4*)(vr + d4 * 4);
                acc[d4*4+0] += pw * vv.x;
                acc[d4*4+1] += pw * vv.y;
                acc[d4*4+2] += pw * vv.z;
                acc[d4*4+3] += pw * vv.w;
            }
        }
    }

    const float inv = 1.0f / lrun;
    float* op = out + (((size_t)(b * SS + p) * HH + h) * DD);
    #pragma unroll
    for (int d4 = 0; d4 < 16; d4++) {
        float4 o;
        o.x = acc[d4*4+0] * inv;
        o.y = acc[d4*4+1] * inv;
        o.z = acc[d4*4+2] * inv;
        o.w = acc[d4*4+3] * inv;
        *(float4*)(op + d4 * 4) = o;
    }
}

// ---------------------------------------------------------------------------
// Tail: next_k / next_v = last window of k / v, layout (B, W, H, D)
// ---------------------------------------------------------------------------
__global__ __launch_bounds__(256) void tail_kernel(float* __restrict__ out)
{
    const size_t OFF_K = (size_t)BB * SS * HH * DD;             // 4194304
    const size_t OFF_V = OFF_K + (size_t)BB * WW * HH * DD;     // 4718592
    int i = blockIdx.x * 256 + threadIdx.x;                     // < 524288
    int b = i / (WW * HH * DD);
    int r = i % (WW * HH * DD);
    int w = r / (HH * DD);
    int r2 = r % (HH * DD);
    int h = r2 / DD;
    int d = r2 % DD;
    size_t src = (((size_t)(b * HH + h) * SS + (SS - WW + w)) * DD + d);
    out[OFF_K + i] = g_k[src];
    out[OFF_V + i] = g_v[src];
}

// ---------------------------------------------------------------------------
extern "C" void kernel_launch(void* const* d_in, const int* in_sizes, int n_in,
                              void* d_out, int out_size)
{
    const float* xs       = (const float*)d_in[0];
    const float* prev_k   = (const float*)d_in[1];
    const float* prev_v   = (const float*)d_in[2];
    const float* w_q      = (const float*)d_in[3];
    const float* w_k      = (const float*)d_in[4];
    const float* w_v      = (const float*)d_in[5];
    const float* rel_bias = (const float*)d_in[6];
    float* out = (float*)d_out;

    static bool attr_set = false;
    if (!attr_set) {
        cudaFuncSetAttribute(proj_kernel,
                             cudaFuncAttributeMaxDynamicSharedMemorySize, 65536);
        attr_set = true;
    }

    split_xs_kernel<<<BB*SS*EE/256, 256>>>(xs);
    split_w_kernel<<<dim3(16, 16, 3), 256>>>(w_q, w_k, w_v);

    dim3 pg(64, 4, 3);                 // M/128, N/128, {q,k,v}
    proj_kernel<<<pg, 256, 65536>>>();

    dim3 ag(4, HH, BB * NWIN);         // query chunks, heads, batch*windows
    attn_kernel<<<ag, 128>>>(prev_k, prev_v, rel_bias, out);

    tail_kernel<<<2048, 256>>>(out);
}